// round 14
// baseline (speedup 1.0000x reference)
#include <cuda_runtime.h>
#include <cuda_fp16.h>
#include <cstdint>

#define HW 16384
#define PCH 136                    // elems per 128-k chunk row (128 + 8 pad)
#define CHUNK (128*PCH)            // elems per 128-row chunk
#define CHUNK_B (CHUNK*2)          // bytes per chunk (34816)
#define FUSE_SMEM (3*CHUNK_B)      // Bs 2 chunks + As 1 chunk = 104448 B

// ---------------- scratch (device globals; no allocations allowed) ----------
__device__ __half g_qkvT[(size_t)8*HW*768];   // [bv][p][768] fp16
__device__ __half g_wqkv[768*256];
__device__ __half g_wproj[256*256];
__device__ float g_part[64][8][2];
__device__ float g_mean[64];
__device__ float g_rstd[64];

// ---------------- helpers ----------------------------------------------------
__device__ __forceinline__ uint32_t s2u(const void* p){
    return (uint32_t)__cvta_generic_to_shared(p);
}
__device__ __forceinline__ void ldsm4(uint32_t r[4], uint32_t addr){
    asm volatile("ldmatrix.sync.aligned.m8n8.x4.shared.b16 {%0,%1,%2,%3}, [%4];"
        : "=r"(r[0]), "=r"(r[1]), "=r"(r[2]), "=r"(r[3]) : "r"(addr));
}
// fp16 inputs, fp16 accumulate (qkv path)
__device__ __forceinline__ void mma_h(uint32_t c[2], const uint32_t a[4],
                                      uint32_t b0, uint32_t b1){
    asm volatile(
      "mma.sync.aligned.m16n8k16.row.col.f16.f16.f16.f16 "
      "{%0,%1},{%2,%3,%4,%5},{%6,%7},{%0,%1};\n"
      : "+r"(c[0]), "+r"(c[1])
      : "r"(a[0]), "r"(a[1]), "r"(a[2]), "r"(a[3]), "r"(b0), "r"(b1));
}
// fp16 inputs, fp32 accumulate (proj path)
__device__ __forceinline__ void mma_f(float c[4], const uint32_t a[4],
                                      uint32_t b0, uint32_t b1){
    asm volatile(
      "mma.sync.aligned.m16n8k16.row.col.f32.f16.f16.f32 "
      "{%0,%1,%2,%3},{%4,%5,%6,%7},{%8,%9},{%0,%1,%2,%3};\n"
      : "+f"(c[0]), "+f"(c[1]), "+f"(c[2]), "+f"(c[3])
      : "r"(a[0]), "r"(a[1]), "r"(a[2]), "r"(a[3]), "r"(b0), "r"(b1));
}

// load a [128 rows][128 k] fp16 half-K weight tile into smem [128][PCH].
// NT = threads in block.
template<int NT>
__device__ __forceinline__ void loadA(__half* As, const __half* W, int t){
    #pragma unroll
    for (int it = 0; it < 2048/NT; ++it){
        const int lin = it*NT + t;
        const int r = lin >> 4, seg = lin & 15;
        *(uint4*)(As + r*PCH + seg*8) = *(const uint4*)(W + r*256 + seg*8);
    }
}

// ---------------- weight convert ---------------------------------------------
__global__ void k_convert(const float* __restrict__ wq, const float* __restrict__ wp){
    int i = blockIdx.x*256 + threadIdx.x;
    if (i < 768*256) g_wqkv[i]  = __float2half(wq[i]);
    if (i < 256*256) g_wproj[i] = __float2half(wp[i]);
}

// ---------------- GroupNorm statistics ---------------------------------------
__global__ void k_stats(const float* __restrict__ x){
    const int gi = blockIdx.x, ck = blockIdx.y, t = threadIdx.x;
    const float4* p = (const float4*)(x + (size_t)gi*524288 + (size_t)ck*65536);
    float s = 0.f, ss = 0.f;
    #pragma unroll 4
    for (int it = 0; it < 64; ++it){
        float4 v = p[it*256 + t];
        s  += v.x + v.y + v.z + v.w;
        ss += v.x*v.x + v.y*v.y + v.z*v.z + v.w*v.w;
    }
    #pragma unroll
    for (int d = 16; d; d >>= 1){
        s  += __shfl_xor_sync(0xffffffffu, s, d);
        ss += __shfl_xor_sync(0xffffffffu, ss, d);
    }
    __shared__ float sh[16];
    if ((t & 31) == 0){ sh[t>>5] = s; sh[8 + (t>>5)] = ss; }
    __syncthreads();
    if (t == 0){
        float S = 0.f, SS = 0.f;
        for (int i = 0; i < 8; ++i){ S += sh[i]; SS += sh[8+i]; }
        g_part[gi][ck][0] = S; g_part[gi][ck][1] = SS;
    }
}

__global__ void k_statfin(){
    const int t = threadIdx.x;
    float S = 0.f, SS = 0.f;
    for (int i = 0; i < 8; ++i){ S += g_part[t][i][0]; SS += g_part[t][i][1]; }
    const float inv = 1.f/524288.f;
    const float m = S*inv;
    const float v = SS*inv - m*m;
    g_mean[t] = m;
    g_rstd[t] = rsqrtf(v + 1e-5f);
}

// ---------------- fused GroupNorm-apply + QKV GEMM ---------------------------
// 128 threads / 4 warps, 2 CTAs/SM (smem 102KB). CTA tile 128 tok x 128 m
// (6 M-iters), K in 2 chunks of 128. Warp tile 64 tok x 64 m (8 LDSM.x4 per
// 32 MMAs). fp16 accumulate + double-buffered fragments (~165 regs, cap 255).
// D = [tok][m] -> direct half2 token-major stores.
__global__ __launch_bounds__(128, 2) void k_qkv(
    const float* __restrict__ x, const float* __restrict__ gamma,
    const float* __restrict__ beta, const float* __restrict__ bqkv)
{
    extern __shared__ __half sm[];
    __half* Bs = sm;               // [2 kc][128 tok][PCH]
    __half* As = sm + 2*CHUNK;     // [128 m][PCH]
    const int t  = threadIdx.x;
    const int bv = blockIdx.y;
    const int p0 = blockIdx.x * 128;
    const int lane = t & 31, warp = t >> 5;

    // ---- fill Bs: normalize x -> fp16, token-major rows, 2 K-chunks ----
    #pragma unroll
    for (int it = 0; it < 32; ++it){
        const int c = (it*4 + warp) * 2;
        const int gidx = bv*8 + (c >> 5);
        const float mu = g_mean[gidx], r = g_rstd[gidx];
        const float sc0 = r*gamma[c],   sh0 = beta[c]   - mu*sc0;
        const float sc1 = r*gamma[c+1], sh1 = beta[c+1] - mu*sc1;
        const float* x0 = x + ((size_t)(bv*256 + c))*HW + p0;
        const float* x1 = x0 + HW;
        __half* dst = Bs + (c >> 7)*CHUNK + (c & 127);
        #pragma unroll
        for (int i = 0; i < 4; ++i){
            const int j = i*32 + lane;
            *(__half2*)(dst + j*PCH) =
                __floats2half2_rn(x0[j]*sc0 + sh0, x1[j]*sc1 + sh1);
        }
    }
    loadA<128>(As, g_wqkv, t);     // (mt=0, kc=0)
    __syncthreads();

    const int g = lane >> 2, tq = lane & 3;
    const int lrow  = lane & 15;
    const int khalf = lane >> 4;
    const int twarp = (warp >> 1) * 64;   // token offset (2 groups of 64)
    const int mwarp = (warp & 1) * 64;    // m offset     (2 groups of 64)

    uint32_t aB[4], bB[4];
    #pragma unroll
    for (int i = 0; i < 4; ++i)
        aB[i] = s2u(Bs + (twarp + i*16 + lrow)*PCH) + khalf*16;
    #pragma unroll
    for (int j = 0; j < 4; ++j)
        bB[j] = s2u(As + (mwarp + j*16 + lrow)*PCH) + khalf*16;

    #pragma unroll 1
    for (int mt = 0; mt < 6; ++mt){
        uint32_t acc[4][8][2];
        #pragma unroll
        for (int i=0;i<4;i++)
            #pragma unroll
            for (int j=0;j<8;j++){ acc[i][j][0]=0u; acc[i][j][1]=0u; }

        #pragma unroll 1
        for (int kc = 0; kc < 2; ++kc){
            const uint32_t boff = (uint32_t)kc * CHUNK_B;
            uint32_t ra[2][4][4], rb[2][4][4];
            #pragma unroll
            for (int i = 0; i < 4; ++i) ldsm4(ra[0][i], aB[i] + boff);
            #pragma unroll
            for (int j = 0; j < 4; ++j) ldsm4(rb[0][j], bB[j]);
            #pragma unroll
            for (int ks = 0; ks < 8; ++ks){
                const int cur = ks & 1, nxt = cur ^ 1;
                if (ks < 7){
                    #pragma unroll
                    for (int i = 0; i < 4; ++i) ldsm4(ra[nxt][i], aB[i] + boff + (ks+1)*32);
                    #pragma unroll
                    for (int j = 0; j < 4; ++j) ldsm4(rb[nxt][j], bB[j] + (ks+1)*32);
                }
                #pragma unroll
                for (int i = 0; i < 4; ++i)
                    #pragma unroll
                    for (int j = 0; j < 8; ++j)
                        mma_h(acc[i][j], ra[cur][i],
                              rb[cur][j>>1][j&1], rb[cur][j>>1][2 + (j&1)]);
            }
            __syncthreads();
            if (kc == 0){
                loadA<128>(As, g_wqkv + (size_t)mt*128*256 + 128, t);
            } else if (mt < 5){
                loadA<128>(As, g_wqkv + (size_t)(mt + 1)*128*256, t);
            }
            if (kc == 1){
                const float* bb = bqkv + mt*128 + mwarp;
                #pragma unroll
                for (int i = 0; i < 4; ++i){
                    const int tokA = p0 + twarp + i*16 + g;
                    __half* d0 = g_qkvT + ((size_t)(bv*HW + tokA))*768 + mt*128 + mwarp;
                    __half* d1 = d0 + (size_t)8*768;
                    #pragma unroll
                    for (int j = 0; j < 8; ++j){
                        const int m0 = j*8 + tq*2;
                        const __half2 b2 = __floats2half2_rn(bb[m0], bb[m0+1]);
                        *(__half2*)(d0 + m0) = __hadd2(*(__half2*)&acc[i][j][0], b2);
                        *(__half2*)(d1 + m0) = __hadd2(*(__half2*)&acc[i][j][1], b2);
                    }
                }
            }
            __syncthreads();
        }
    }
}

// ---------------- fused attention + proj GEMM + bias + residual ---------------
// CTA: one batch-pair x 64 pixels (128 tokens, view-major). 256 threads,
// 2 CTAs/SM. Phase 1: warp-per-pixel attention -> ao into Bs K-chunks.
// Phase 2: proj GEMM 128 tok x 256 ch (2 M-iters, 2 K-chunks), fp32 accum,
// warp tile 32ch x 64tok; fused bias + residual + direct float2 NCHW stores.
__global__ __launch_bounds__(256, 2) void k_proj(
    const float* __restrict__ x, const float* __restrict__ bproj, float* __restrict__ out)
{
    extern __shared__ __half sm[];
    __half* Bs = sm;               // [2 kc][128 tok][PCH] attention out
    __half* As = sm + 2*CHUNK;     // [128 ch][PCH] weights
    const int t  = threadIdx.x;
    const int b  = blockIdx.y;            // pair index
    const int p0 = blockIdx.x * 64;
    const int lane = t & 31, warp = t >> 5;

    // ---- phase 1: attention (8 pixels per warp) ----
    {
        const int off = (lane >> 3)*64 + (lane & 7)*8;   // channel offset 0..255
        const int chunk = off >> 7, cin = off & 127;
        #pragma unroll 2
        for (int itr = 0; itr < 8; ++itr){
            const int pix = warp*8 + itr;
            const __half* r0 = g_qkvT + ((size_t)(b*2*HW + p0 + pix))*768;
            const __half* r1 = r0 + (size_t)HW*768;
            float q0[8],q1[8],k0[8],k1[8],v0[8],v1[8];
            {
                uint4 u; const __half2* h = (const __half2*)&u; float2 f;
                #define LD8(dst, ptr) { u = *(const uint4*)(ptr); \
                    _Pragma("unroll") for (int e = 0; e < 4; ++e){ f = __half22float2(h[e]); dst[2*e]=f.x; dst[2*e+1]=f.y; } }
                LD8(q0, r0 + off);        LD8(q1, r1 + off);
                LD8(k0, r0 + 256 + off);  LD8(k1, r1 + 256 + off);
                LD8(v0, r0 + 512 + off);  LD8(v1, r1 + 512 + off);
                #undef LD8
            }
            float s00=0.f, s01=0.f, s10=0.f, s11=0.f;
            #pragma unroll
            for (int j = 0; j < 8; ++j){
                s00 += q0[j]*k0[j]; s01 += q0[j]*k1[j];
                s10 += q1[j]*k0[j]; s11 += q1[j]*k1[j];
            }
            #pragma unroll
            for (int d = 1; d < 8; d <<= 1){
                s00 += __shfl_xor_sync(0xffffffffu, s00, d);
                s01 += __shfl_xor_sync(0xffffffffu, s01, d);
                s10 += __shfl_xor_sync(0xffffffffu, s10, d);
                s11 += __shfl_xor_sync(0xffffffffu, s11, d);
            }
            const float sc = 0.125f;
            const float l00=s00*sc, l01=s01*sc, l10=s10*sc, l11=s11*sc;
            const float m0 = fmaxf(l00,l01), m1 = fmaxf(l10,l11);
            const float e00=__expf(l00-m0), e01=__expf(l01-m0);
            const float e10=__expf(l10-m1), e11=__expf(l11-m1);
            const float i0 = 1.f/(e00+e01), i1 = 1.f/(e10+e11);
            const float a00=e00*i0, a01=e01*i0, a10=e10*i1, a11=e11*i1;
            __align__(16) __half o0[8], o1[8];
            #pragma unroll
            for (int j = 0; j < 8; ++j){
                o0[j] = __float2half(a00*v0[j] + a01*v1[j]);
                o1[j] = __float2half(a10*v0[j] + a11*v1[j]);
            }
            *(uint4*)(Bs + chunk*CHUNK + pix*PCH + cin)        = *(const uint4*)o0;
            *(uint4*)(Bs + chunk*CHUNK + (64 + pix)*PCH + cin) = *(const uint4*)o1;
        }
    }
    loadA<256>(As, g_wproj, t);    // (mt=0, kc=0)
    __syncthreads();

    // ---- phase 2: proj GEMM (fp32 accumulate) ----
    const int g = lane >> 2, tq = lane & 3;
    const int lrow  = lane & 15;
    const int khalf = lane >> 4;
    const int mwarp = (warp & 3) * 32;    // channel offset (4 groups of 32)
    const int twarp = (warp >> 2) * 64;   // token offset (view0/view1)
    const int view  = warp >> 2;

    uint32_t aB[2], bB[4];
    #pragma unroll
    for (int i = 0; i < 2; ++i)
        aB[i] = s2u(As + (mwarp + i*16 + lrow)*PCH) + khalf*16;
    #pragma unroll
    for (int j = 0; j < 4; ++j)
        bB[j] = s2u(Bs + (twarp + j*16 + lrow)*PCH) + khalf*16;

    #pragma unroll 1
    for (int mt = 0; mt < 2; ++mt){
        float acc[2][8][4];
        #pragma unroll
        for (int i=0;i<2;i++)
            #pragma unroll
            for (int j=0;j<8;j++)
                #pragma unroll
                for (int r=0;r<4;r++) acc[i][j][r]=0.f;

        #pragma unroll 1
        for (int kc = 0; kc < 2; ++kc){
            const uint32_t boff = (uint32_t)kc * CHUNK_B;
            #pragma unroll
            for (int ks = 0; ks < 8; ++ks){
                uint32_t ra[2][4], rb[4][4];
                #pragma unroll
                for (int i = 0; i < 2; ++i) ldsm4(ra[i], aB[i] + ks*32);
                #pragma unroll
                for (int j = 0; j < 4; ++j) ldsm4(rb[j], bB[j] + boff + ks*32);
                #pragma unroll
                for (int i = 0; i < 2; ++i)
                    #pragma unroll
                    for (int j = 0; j < 8; ++j)
                        mma_f(acc[i][j], ra[i],
                              rb[j>>1][j&1], rb[j>>1][2 + (j&1)]);
            }
            __syncthreads();
            if (kc == 0){
                loadA<256>(As, g_wproj + (size_t)mt*128*256 + 128, t);
            } else if (mt == 0){
                loadA<256>(As, g_wproj + (size_t)128*256, t);
            }
            if (kc == 1){
                #pragma unroll
                for (int i = 0; i < 2; ++i){
                    const int ch0 = mt*128 + mwarp + i*16 + g;
                    const int ch1 = ch0 + 8;
                    const float b0 = bproj[ch0], b1 = bproj[ch1];
                    const size_t base0 = ((size_t)((b*2 + view)*256 + ch0))*HW + p0;
                    const size_t base1 = ((size_t)((b*2 + view)*256 + ch1))*HW + p0;
                    #pragma unroll
                    for (int j = 0; j < 8; ++j){
                        const int tk = j*8 + tq*2;
                        float2 xv0 = *(const float2*)(x + base0 + tk);
                        float2 xv1 = *(const float2*)(x + base1 + tk);
                        *(float2*)(out + base0 + tk) =
                            make_float2(xv0.x + acc[i][j][0] + b0, xv0.y + acc[i][j][1] + b0);
                        *(float2*)(out + base1 + tk) =
                            make_float2(xv1.x + acc[i][j][2] + b1, xv1.y + acc[i][j][3] + b1);
                    }
                }
            }
            __syncthreads();
        }
    }
}

// ---------------- launch -------------------------------------------------------
extern "C" void kernel_launch(void* const* d_in, const int* in_sizes, int n_in,
                              void* d_out, int out_size)
{
    const float* x     = (const float*)d_in[0];
    const float* gam   = (const float*)d_in[1];
    const float* bet   = (const float*)d_in[2];
    const float* wqkv  = (const float*)d_in[3];
    const float* bqkv  = (const float*)d_in[4];
    const float* wproj = (const float*)d_in[5];
    const float* bproj = (const float*)d_in[6];
    float* out = (float*)d_out;

    cudaFuncSetAttribute(k_qkv,  cudaFuncAttributeMaxDynamicSharedMemorySize, FUSE_SMEM);
    cudaFuncSetAttribute(k_proj, cudaFuncAttributeMaxDynamicSharedMemorySize, FUSE_SMEM);

    k_convert<<<768, 256>>>(wqkv, wproj);
    k_stats<<<dim3(64, 8), 256>>>(x);
    k_statfin<<<1, 64>>>();
    k_qkv<<<dim3(128, 8), 128, FUSE_SMEM>>>(x, gam, bet, bqkv);
    k_proj<<<dim3(256, 4), 256, FUSE_SMEM>>>(x, bproj, out);
}

// round 15
// speedup vs baseline: 1.0225x; 1.0225x over previous
#include <cuda_runtime.h>
#include <cuda_fp16.h>
#include <cstdint>

#define HW 16384
#define PCH 136                    // elems per 128-k chunk row (128 + 8 pad)
#define CHUNK (128*PCH)            // elems per 128-row chunk
#define CHUNK_B (CHUNK*2)          // bytes per chunk (34816)
#define FUSE_SMEM (3*CHUNK_B)      // Bs 2 chunks + As 1 chunk = 104448 B

// ---------------- scratch (device globals; no allocations allowed) ----------
__device__ __half g_qkvT[(size_t)8*HW*768];   // [bv][p][768] fp16
__device__ __half g_wqkv[768*256];
__device__ __half g_wproj[256*256];
__device__ float g_part[64][8][2];
__device__ float g_mean[64];
__device__ float g_rstd[64];

// ---------------- helpers ----------------------------------------------------
__device__ __forceinline__ uint32_t s2u(const void* p){
    return (uint32_t)__cvta_generic_to_shared(p);
}
__device__ __forceinline__ void ldsm4(uint32_t r[4], uint32_t addr){
    asm volatile("ldmatrix.sync.aligned.m8n8.x4.shared.b16 {%0,%1,%2,%3}, [%4];"
        : "=r"(r[0]), "=r"(r[1]), "=r"(r[2]), "=r"(r[3]) : "r"(addr));
}
// fp16 inputs, fp16 accumulate (qkv path)
__device__ __forceinline__ void mma_h(uint32_t c[2], const uint32_t a[4],
                                      uint32_t b0, uint32_t b1){
    asm volatile(
      "mma.sync.aligned.m16n8k16.row.col.f16.f16.f16.f16 "
      "{%0,%1},{%2,%3,%4,%5},{%6,%7},{%0,%1};\n"
      : "+r"(c[0]), "+r"(c[1])
      : "r"(a[0]), "r"(a[1]), "r"(a[2]), "r"(a[3]), "r"(b0), "r"(b1));
}
// fp16 inputs, fp32 accumulate (proj path)
__device__ __forceinline__ void mma_f(float c[4], const uint32_t a[4],
                                      uint32_t b0, uint32_t b1){
    asm volatile(
      "mma.sync.aligned.m16n8k16.row.col.f32.f16.f16.f32 "
      "{%0,%1,%2,%3},{%4,%5,%6,%7},{%8,%9},{%0,%1,%2,%3};\n"
      : "+f"(c[0]), "+f"(c[1]), "+f"(c[2]), "+f"(c[3])
      : "r"(a[0]), "r"(a[1]), "r"(a[2]), "r"(a[3]), "r"(b0), "r"(b1));
}

// load a [128 rows][128 k] fp16 half-K weight tile into smem [128][PCH].
template<int NT>
__device__ __forceinline__ void loadA(__half* As, const __half* W, int t){
    #pragma unroll
    for (int it = 0; it < 2048/NT; ++it){
        const int lin = it*NT + t;
        const int r = lin >> 4, seg = lin & 15;
        *(uint4*)(As + r*PCH + seg*8) = *(const uint4*)(W + r*256 + seg*8);
    }
}

// ---------------- weight convert ---------------------------------------------
__global__ void k_convert(const float* __restrict__ wq, const float* __restrict__ wp){
    int i = blockIdx.x*256 + threadIdx.x;
    if (i < 768*256) g_wqkv[i]  = __float2half(wq[i]);
    if (i < 256*256) g_wproj[i] = __float2half(wp[i]);
}

// ---------------- GroupNorm statistics ---------------------------------------
__global__ void k_stats(const float* __restrict__ x){
    const int gi = blockIdx.x, ck = blockIdx.y, t = threadIdx.x;
    const float4* p = (const float4*)(x + (size_t)gi*524288 + (size_t)ck*65536);
    float s = 0.f, ss = 0.f;
    #pragma unroll 4
    for (int it = 0; it < 64; ++it){
        float4 v = p[it*256 + t];
        s  += v.x + v.y + v.z + v.w;
        ss += v.x*v.x + v.y*v.y + v.z*v.z + v.w*v.w;
    }
    #pragma unroll
    for (int d = 16; d; d >>= 1){
        s  += __shfl_xor_sync(0xffffffffu, s, d);
        ss += __shfl_xor_sync(0xffffffffu, ss, d);
    }
    __shared__ float sh[16];
    if ((t & 31) == 0){ sh[t>>5] = s; sh[8 + (t>>5)] = ss; }
    __syncthreads();
    if (t == 0){
        float S = 0.f, SS = 0.f;
        for (int i = 0; i < 8; ++i){ S += sh[i]; SS += sh[8+i]; }
        g_part[gi][ck][0] = S; g_part[gi][ck][1] = SS;
    }
}

__global__ void k_statfin(){
    const int t = threadIdx.x;
    float S = 0.f, SS = 0.f;
    for (int i = 0; i < 8; ++i){ S += g_part[t][i][0]; SS += g_part[t][i][1]; }
    const float inv = 1.f/524288.f;
    const float m = S*inv;
    const float v = SS*inv - m*m;
    g_mean[t] = m;
    g_rstd[t] = rsqrtf(v + 1e-5f);
}

// ---------------- fused GroupNorm-apply + QKV GEMM ---------------------------
// 256 threads / 8 warps, 2 CTAs/SM (smem 102KB, regs ~110<=128).
// CTA tile 128 tok x 128 m (6 M-iters), K in 2 chunks of 128.
// Warp tile 64 tok x 32 m, fp16 accumulate, DOUBLE-BUFFERED fragments.
// D = [tok][m] -> direct half2 token-major stores.
__global__ __launch_bounds__(256, 2) void k_qkv(
    const float* __restrict__ x, const float* __restrict__ gamma,
    const float* __restrict__ beta, const float* __restrict__ bqkv)
{
    extern __shared__ __half sm[];
    __half* Bs = sm;               // [2 kc][128 tok][PCH]
    __half* As = sm + 2*CHUNK;     // [128 m][PCH]
    const int t  = threadIdx.x;
    const int bv = blockIdx.y;
    const int p0 = blockIdx.x * 128;
    const int lane = t & 31, warp = t >> 5;

    // ---- fill Bs: normalize x -> fp16, token-major rows, 2 K-chunks ----
    #pragma unroll
    for (int it = 0; it < 16; ++it){
        const int c = (it*8 + warp) * 2;
        const int gidx = bv*8 + (c >> 5);
        const float mu = g_mean[gidx], r = g_rstd[gidx];
        const float sc0 = r*gamma[c],   sh0 = beta[c]   - mu*sc0;
        const float sc1 = r*gamma[c+1], sh1 = beta[c+1] - mu*sc1;
        const float* x0 = x + ((size_t)(bv*256 + c))*HW + p0;
        const float* x1 = x0 + HW;
        __half* dst = Bs + (c >> 7)*CHUNK + (c & 127);
        #pragma unroll
        for (int i = 0; i < 4; ++i){
            const int j = i*32 + lane;
            *(__half2*)(dst + j*PCH) =
                __floats2half2_rn(x0[j]*sc0 + sh0, x1[j]*sc1 + sh1);
        }
    }
    loadA<256>(As, g_wqkv, t);     // (mt=0, kc=0)
    __syncthreads();

    const int g = lane >> 2, tq = lane & 3;
    const int lrow  = lane & 15;
    const int khalf = lane >> 4;
    const int twarp = (warp >> 2) * 64;   // token offset (2 groups of 64)
    const int mwarp = (warp & 3) * 32;    // m offset     (4 groups of 32)

    uint32_t aB[4], bB[2];
    #pragma unroll
    for (int i = 0; i < 4; ++i)
        aB[i] = s2u(Bs + (twarp + i*16 + lrow)*PCH) + khalf*16;
    #pragma unroll
    for (int j = 0; j < 2; ++j)
        bB[j] = s2u(As + (mwarp + j*16 + lrow)*PCH) + khalf*16;

    #pragma unroll 1
    for (int mt = 0; mt < 6; ++mt){
        uint32_t acc[4][4][2];
        #pragma unroll
        for (int i=0;i<4;i++)
            #pragma unroll
            for (int j=0;j<4;j++){ acc[i][j][0]=0u; acc[i][j][1]=0u; }

        #pragma unroll 1
        for (int kc = 0; kc < 2; ++kc){
            const uint32_t boff = (uint32_t)kc * CHUNK_B;
            uint32_t ra[2][4][4], rb[2][2][4];
            #pragma unroll
            for (int i = 0; i < 4; ++i) ldsm4(ra[0][i], aB[i] + boff);
            #pragma unroll
            for (int j = 0; j < 2; ++j) ldsm4(rb[0][j], bB[j]);
            #pragma unroll
            for (int ks = 0; ks < 8; ++ks){
                const int cur = ks & 1, nxt = cur ^ 1;
                if (ks < 7){
                    #pragma unroll
                    for (int i = 0; i < 4; ++i) ldsm4(ra[nxt][i], aB[i] + boff + (ks+1)*32);
                    #pragma unroll
                    for (int j = 0; j < 2; ++j) ldsm4(rb[nxt][j], bB[j] + (ks+1)*32);
                }
                #pragma unroll
                for (int i = 0; i < 4; ++i)
                    #pragma unroll
                    for (int j = 0; j < 4; ++j)
                        mma_h(acc[i][j], ra[cur][i],
                              rb[cur][j>>1][j&1], rb[cur][j>>1][2 + (j&1)]);
            }
            __syncthreads();
            if (kc == 0){
                loadA<256>(As, g_wqkv + (size_t)mt*128*256 + 128, t);
            } else if (mt < 5){
                loadA<256>(As, g_wqkv + (size_t)(mt + 1)*128*256, t);
            }
            if (kc == 1){
                const float* bb = bqkv + mt*128 + mwarp;
                #pragma unroll
                for (int i = 0; i < 4; ++i){
                    const int tokA = p0 + twarp + i*16 + g;
                    __half* d0 = g_qkvT + ((size_t)(bv*HW + tokA))*768 + mt*128 + mwarp;
                    __half* d1 = d0 + (size_t)8*768;
                    #pragma unroll
                    for (int j = 0; j < 4; ++j){
                        const int m0 = j*8 + tq*2;
                        const __half2 b2 = __floats2half2_rn(bb[m0], bb[m0+1]);
                        *(__half2*)(d0 + m0) = __hadd2(*(__half2*)&acc[i][j][0], b2);
                        *(__half2*)(d1 + m0) = __hadd2(*(__half2*)&acc[i][j][1], b2);
                    }
                }
            }
            __syncthreads();
        }
    }
}

// ---------------- fused attention + proj GEMM + bias + residual ---------------
// CTA: one batch-pair x 64 pixels (128 tokens, view-major). 256 threads,
// 2 CTAs/SM. Phase 1: warp-per-pixel attention -> ao into Bs K-chunks.
// Phase 2: proj GEMM 128 tok x 256 ch (2 M-iters, 2 K-chunks), fp32 accum,
// warp tile 32ch x 64tok; fused bias + residual + direct float2 NCHW stores.
__global__ __launch_bounds__(256, 2) void k_proj(
    const float* __restrict__ x, const float* __restrict__ bproj, float* __restrict__ out)
{
    extern __shared__ __half sm[];
    __half* Bs = sm;               // [2 kc][128 tok][PCH] attention out
    __half* As = sm + 2*CHUNK;     // [128 ch][PCH] weights
    const int t  = threadIdx.x;
    const int b  = blockIdx.y;            // pair index
    const int p0 = blockIdx.x * 64;
    const int lane = t & 31, warp = t >> 5;

    // ---- phase 1: attention (8 pixels per warp) ----
    {
        const int off = (lane >> 3)*64 + (lane & 7)*8;   // channel offset 0..255
        const int chunk = off >> 7, cin = off & 127;
        #pragma unroll 2
        for (int itr = 0; itr < 8; ++itr){
            const int pix = warp*8 + itr;
            const __half* r0 = g_qkvT + ((size_t)(b*2*HW + p0 + pix))*768;
            const __half* r1 = r0 + (size_t)HW*768;
            float q0[8],q1[8],k0[8],k1[8],v0[8],v1[8];
            {
                uint4 u; const __half2* h = (const __half2*)&u; float2 f;
                #define LD8(dst, ptr) { u = *(const uint4*)(ptr); \
                    _Pragma("unroll") for (int e = 0; e < 4; ++e){ f = __half22float2(h[e]); dst[2*e]=f.x; dst[2*e+1]=f.y; } }
                LD8(q0, r0 + off);        LD8(q1, r1 + off);
                LD8(k0, r0 + 256 + off);  LD8(k1, r1 + 256 + off);
                LD8(v0, r0 + 512 + off);  LD8(v1, r1 + 512 + off);
                #undef LD8
            }
            float s00=0.f, s01=0.f, s10=0.f, s11=0.f;
            #pragma unroll
            for (int j = 0; j < 8; ++j){
                s00 += q0[j]*k0[j]; s01 += q0[j]*k1[j];
                s10 += q1[j]*k0[j]; s11 += q1[j]*k1[j];
            }
            #pragma unroll
            for (int d = 1; d < 8; d <<= 1){
                s00 += __shfl_xor_sync(0xffffffffu, s00, d);
                s01 += __shfl_xor_sync(0xffffffffu, s01, d);
                s10 += __shfl_xor_sync(0xffffffffu, s10, d);
                s11 += __shfl_xor_sync(0xffffffffu, s11, d);
            }
            const float sc = 0.125f;
            const float l00=s00*sc, l01=s01*sc, l10=s10*sc, l11=s11*sc;
            const float m0 = fmaxf(l00,l01), m1 = fmaxf(l10,l11);
            const float e00=__expf(l00-m0), e01=__expf(l01-m0);
            const float e10=__expf(l10-m1), e11=__expf(l11-m1);
            const float i0 = 1.f/(e00+e01), i1 = 1.f/(e10+e11);
            const float a00=e00*i0, a01=e01*i0, a10=e10*i1, a11=e11*i1;
            __align__(16) __half o0[8], o1[8];
            #pragma unroll
            for (int j = 0; j < 8; ++j){
                o0[j] = __float2half(a00*v0[j] + a01*v1[j]);
                o1[j] = __float2half(a10*v0[j] + a11*v1[j]);
            }
            *(uint4*)(Bs + chunk*CHUNK + pix*PCH + cin)        = *(const uint4*)o0;
            *(uint4*)(Bs + chunk*CHUNK + (64 + pix)*PCH + cin) = *(const uint4*)o1;
        }
    }
    loadA<256>(As, g_wproj, t);    // (mt=0, kc=0)
    __syncthreads();

    // ---- phase 2: proj GEMM (fp32 accumulate) ----
    const int g = lane >> 2, tq = lane & 3;
    const int lrow  = lane & 15;
    const int khalf = lane >> 4;
    const int mwarp = (warp & 3) * 32;    // channel offset (4 groups of 32)
    const int twarp = (warp >> 2) * 64;   // token offset (view0/view1)
    const int view  = warp >> 2;

    uint32_t aB[2], bB[4];
    #pragma unroll
    for (int i = 0; i < 2; ++i)
        aB[i] = s2u(As + (mwarp + i*16 + lrow)*PCH) + khalf*16;
    #pragma unroll
    for (int j = 0; j < 4; ++j)
        bB[j] = s2u(Bs + (twarp + j*16 + lrow)*PCH) + khalf*16;

    #pragma unroll 1
    for (int mt = 0; mt < 2; ++mt){
        float acc[2][8][4];
        #pragma unroll
        for (int i=0;i<2;i++)
            #pragma unroll
            for (int j=0;j<8;j++)
                #pragma unroll
                for (int r=0;r<4;r++) acc[i][j][r]=0.f;

        #pragma unroll 1
        for (int kc = 0; kc < 2; ++kc){
            const uint32_t boff = (uint32_t)kc * CHUNK_B;
            #pragma unroll
            for (int ks = 0; ks < 8; ++ks){
                uint32_t ra[2][4], rb[4][4];
                #pragma unroll
                for (int i = 0; i < 2; ++i) ldsm4(ra[i], aB[i] + ks*32);
                #pragma unroll
                for (int j = 0; j < 4; ++j) ldsm4(rb[j], bB[j] + boff + ks*32);
                #pragma unroll
                for (int i = 0; i < 2; ++i)
                    #pragma unroll
                    for (int j = 0; j < 8; ++j)
                        mma_f(acc[i][j], ra[i],
                              rb[j>>1][j&1], rb[j>>1][2 + (j&1)]);
            }
            __syncthreads();
            if (kc == 0){
                loadA<256>(As, g_wproj + (size_t)mt*128*256 + 128, t);
            } else if (mt == 0){
                loadA<256>(As, g_wproj + (size_t)128*256, t);
            }
            if (kc == 1){
                #pragma unroll
                for (int i = 0; i < 2; ++i){
                    const int ch0 = mt*128 + mwarp + i*16 + g;
                    const int ch1 = ch0 + 8;
                    const float b0 = bproj[ch0], b1 = bproj[ch1];
                    const size_t base0 = ((size_t)((b*2 + view)*256 + ch0))*HW + p0;
                    const size_t base1 = ((size_t)((b*2 + view)*256 + ch1))*HW + p0;
                    #pragma unroll
                    for (int j = 0; j < 8; ++j){
                        const int tk = j*8 + tq*2;
                        float2 xv0 = *(const float2*)(x + base0 + tk);
                        float2 xv1 = *(const float2*)(x + base1 + tk);
                        *(float2*)(out + base0 + tk) =
                            make_float2(xv0.x + acc[i][j][0] + b0, xv0.y + acc[i][j][1] + b0);
                        *(float2*)(out + base1 + tk) =
                            make_float2(xv1.x + acc[i][j][2] + b1, xv1.y + acc[i][j][3] + b1);
                    }
                }
            }
            __syncthreads();
        }
    }
}

// ---------------- launch -------------------------------------------------------
extern "C" void kernel_launch(void* const* d_in, const int* in_sizes, int n_in,
                              void* d_out, int out_size)
{
    const float* x     = (const float*)d_in[0];
    const float* gam   = (const float*)d_in[1];
    const float* bet   = (const float*)d_in[2];
    const float* wqkv  = (const float*)d_in[3];
    const float* bqkv  = (const float*)d_in[4];
    const float* wproj = (const float*)d_in[5];
    const float* bproj = (const float*)d_in[6];
    float* out = (float*)d_out;

    cudaFuncSetAttribute(k_qkv,  cudaFuncAttributeMaxDynamicSharedMemorySize, FUSE_SMEM);
    cudaFuncSetAttribute(k_proj, cudaFuncAttributeMaxDynamicSharedMemorySize, FUSE_SMEM);

    k_convert<<<768, 256>>>(wqkv, wproj);
    k_stats<<<dim3(64, 8), 256>>>(x);
    k_statfin<<<1, 64>>>();
    k_qkv<<<dim3(128, 8), 256, FUSE_SMEM>>>(x, gam, bet, bqkv);
    k_proj<<<dim3(256, 4), 256, FUSE_SMEM>>>(x, bproj, out);
}

// round 16
// speedup vs baseline: 1.0640x; 1.0407x over previous
#include <cuda_runtime.h>
#include <cuda_fp16.h>
#include <cstdint>

#define HW 16384
#define PCH 136                    // elems per 128-k chunk row (128 + 8 pad)
#define CHUNK (128*PCH)            // elems per 128-row chunk
#define CHUNK_B (CHUNK*2)          // bytes per chunk (34816)
#define FUSE_SMEM (3*CHUNK_B)      // Bs 2 chunks + As 1 chunk = 104448 B

// ---------------- scratch (device globals; no allocations allowed) ----------
__device__ __half g_qkvT[(size_t)8*HW*768];   // [bv][p][768] fp16
__device__ __half g_wqkv[768*256];
__device__ __half g_wproj[256*256];
__device__ __half g_bqkvh[768];
__device__ float g_part[64][8][2];
__device__ float g_mean[64];
__device__ float g_rstd[64];

// ---------------- helpers ----------------------------------------------------
__device__ __forceinline__ uint32_t s2u(const void* p){
    return (uint32_t)__cvta_generic_to_shared(p);
}
__device__ __forceinline__ void ldsm4(uint32_t r[4], uint32_t addr){
    asm volatile("ldmatrix.sync.aligned.m8n8.x4.shared.b16 {%0,%1,%2,%3}, [%4];"
        : "=r"(r[0]), "=r"(r[1]), "=r"(r[2]), "=r"(r[3]) : "r"(addr));
}
// fp16 inputs, fp16 accumulate (qkv path)
__device__ __forceinline__ void mma_h(uint32_t c[2], const uint32_t a[4],
                                      uint32_t b0, uint32_t b1){
    asm volatile(
      "mma.sync.aligned.m16n8k16.row.col.f16.f16.f16.f16 "
      "{%0,%1},{%2,%3,%4,%5},{%6,%7},{%0,%1};\n"
      : "+r"(c[0]), "+r"(c[1])
      : "r"(a[0]), "r"(a[1]), "r"(a[2]), "r"(a[3]), "r"(b0), "r"(b1));
}
// fp16 inputs, fp32 accumulate (proj path)
__device__ __forceinline__ void mma_f(float c[4], const uint32_t a[4],
                                      uint32_t b0, uint32_t b1){
    asm volatile(
      "mma.sync.aligned.m16n8k16.row.col.f32.f16.f16.f32 "
      "{%0,%1,%2,%3},{%4,%5,%6,%7},{%8,%9},{%0,%1,%2,%3};\n"
      : "+f"(c[0]), "+f"(c[1]), "+f"(c[2]), "+f"(c[3])
      : "r"(a[0]), "r"(a[1]), "r"(a[2]), "r"(a[3]), "r"(b0), "r"(b1));
}

// load a [128 rows][128 k] fp16 half-K weight tile into smem [128][PCH].
template<int NT>
__device__ __forceinline__ void loadA(__half* As, const __half* W, int t){
    #pragma unroll
    for (int it = 0; it < 2048/NT; ++it){
        const int lin = it*NT + t;
        const int r = lin >> 4, seg = lin & 15;
        *(uint4*)(As + r*PCH + seg*8) = *(const uint4*)(W + r*256 + seg*8);
    }
}

// ---------------- weight convert ---------------------------------------------
__global__ void k_convert(const float* __restrict__ wq, const float* __restrict__ wp,
                          const float* __restrict__ bq){
    int i = blockIdx.x*256 + threadIdx.x;
    if (i < 768*256) g_wqkv[i]  = __float2half(wq[i]);
    if (i < 256*256) g_wproj[i] = __float2half(wp[i]);
    if (i < 768)     g_bqkvh[i] = __float2half(bq[i]);
}

// ---------------- GroupNorm statistics ---------------------------------------
__global__ void k_stats(const float* __restrict__ x){
    const int gi = blockIdx.x, ck = blockIdx.y, t = threadIdx.x;
    const float4* p = (const float4*)(x + (size_t)gi*524288 + (size_t)ck*65536);
    float s = 0.f, ss = 0.f;
    #pragma unroll 4
    for (int it = 0; it < 64; ++it){
        float4 v = p[it*256 + t];
        s  += v.x + v.y + v.z + v.w;
        ss += v.x*v.x + v.y*v.y + v.z*v.z + v.w*v.w;
    }
    #pragma unroll
    for (int d = 16; d; d >>= 1){
        s  += __shfl_xor_sync(0xffffffffu, s, d);
        ss += __shfl_xor_sync(0xffffffffu, ss, d);
    }
    __shared__ float sh[16];
    if ((t & 31) == 0){ sh[t>>5] = s; sh[8 + (t>>5)] = ss; }
    __syncthreads();
    if (t == 0){
        float S = 0.f, SS = 0.f;
        for (int i = 0; i < 8; ++i){ S += sh[i]; SS += sh[8+i]; }
        g_part[gi][ck][0] = S; g_part[gi][ck][1] = SS;
    }
}

__global__ void k_statfin(){
    const int t = threadIdx.x;
    float S = 0.f, SS = 0.f;
    for (int i = 0; i < 8; ++i){ S += g_part[t][i][0]; SS += g_part[t][i][1]; }
    const float inv = 1.f/524288.f;
    const float m = S*inv;
    const float v = SS*inv - m*m;
    g_mean[t] = m;
    g_rstd[t] = rsqrtf(v + 1e-5f);
}

// ---------------- fused GroupNorm-apply + QKV GEMM ---------------------------
// 256 threads / 8 warps, 2 CTAs/SM. CTA tile 128 tok x 128 m (6 M-iters),
// K in 2 chunks of 128. Warp tile 64 tok x 32 m, fp16 accumulate.
// Epilogue: quad shfl-transpose -> one STG.128 per (i,h) (contiguous 16B),
// bias pre-converted to fp16 (one uint4 load per mt).
__global__ __launch_bounds__(256, 2) void k_qkv(
    const float* __restrict__ x, const float* __restrict__ gamma,
    const float* __restrict__ beta)
{
    extern __shared__ __half sm[];
    __half* Bs = sm;               // [2 kc][128 tok][PCH]
    __half* As = sm + 2*CHUNK;     // [128 m][PCH]
    const int t  = threadIdx.x;
    const int bv = blockIdx.y;
    const int p0 = blockIdx.x * 128;
    const int lane = t & 31, warp = t >> 5;

    // ---- fill Bs: normalize x -> fp16, token-major rows, 2 K-chunks ----
    #pragma unroll
    for (int it = 0; it < 16; ++it){
        const int c = (it*8 + warp) * 2;
        const int gidx = bv*8 + (c >> 5);
        const float mu = g_mean[gidx], r = g_rstd[gidx];
        const float sc0 = r*gamma[c],   sh0 = beta[c]   - mu*sc0;
        const float sc1 = r*gamma[c+1], sh1 = beta[c+1] - mu*sc1;
        const float* x0 = x + ((size_t)(bv*256 + c))*HW + p0;
        const float* x1 = x0 + HW;
        __half* dst = Bs + (c >> 7)*CHUNK + (c & 127);
        #pragma unroll
        for (int i = 0; i < 4; ++i){
            const int j = i*32 + lane;
            *(__half2*)(dst + j*PCH) =
                __floats2half2_rn(x0[j]*sc0 + sh0, x1[j]*sc1 + sh1);
        }
    }
    loadA<256>(As, g_wqkv, t);     // (mt=0, kc=0)
    __syncthreads();

    const int g = lane >> 2, tq = lane & 3;
    const int lrow  = lane & 15;
    const int khalf = lane >> 4;
    const int twarp = (warp >> 2) * 64;   // token offset (2 groups of 64)
    const int mwarp = (warp & 3) * 32;    // m offset     (4 groups of 32)

    uint32_t aB[4], bB[2];
    #pragma unroll
    for (int i = 0; i < 4; ++i)
        aB[i] = s2u(Bs + (twarp + i*16 + lrow)*PCH) + khalf*16;
    #pragma unroll
    for (int j = 0; j < 2; ++j)
        bB[j] = s2u(As + (mwarp + j*16 + lrow)*PCH) + khalf*16;

    #pragma unroll 1
    for (int mt = 0; mt < 6; ++mt){
        uint32_t acc[4][4][2];
        #pragma unroll
        for (int i=0;i<4;i++)
            #pragma unroll
            for (int j=0;j<4;j++){ acc[i][j][0]=0u; acc[i][j][1]=0u; }

        #pragma unroll 1
        for (int kc = 0; kc < 2; ++kc){
            const uint32_t boff = (uint32_t)kc * CHUNK_B;
            #pragma unroll
            for (int ks = 0; ks < 8; ++ks){
                uint32_t ra[4][4], rb[2][4];
                #pragma unroll
                for (int i = 0; i < 4; ++i) ldsm4(ra[i], aB[i] + boff + ks*32);
                #pragma unroll
                for (int j = 0; j < 2; ++j) ldsm4(rb[j], bB[j] + ks*32);
                #pragma unroll
                for (int i = 0; i < 4; ++i)
                    #pragma unroll
                    for (int j = 0; j < 4; ++j)
                        mma_h(acc[i][j], ra[i],
                              rb[j>>1][j&1], rb[j>>1][2 + (j&1)]);
            }
            __syncthreads();
            if (kc == 0){
                loadA<256>(As, g_wqkv + (size_t)mt*128*256 + 128, t);
            } else if (mt < 5){
                loadA<256>(As, g_wqkv + (size_t)(mt + 1)*128*256, t);
            }
            if (kc == 1){
                // quad transpose epilogue: each thread ends with 8 contiguous
                // halves [mwarp + tq*8 .. +8) -> one STG.128 per (i, row-half).
                const uint4 bu = *(const uint4*)(g_bqkvh + mt*128 + mwarp + tq*8);
                const __half2* bb2 = (const __half2*)&bu;
                #pragma unroll
                for (int i = 0; i < 4; ++i){
                    const int tokA = p0 + twarp + i*16 + g;
                    __half* drow = g_qkvT + ((size_t)(bv*HW + tokA))*768
                                 + mt*128 + mwarp + tq*8;
                    #pragma unroll
                    for (int h = 0; h < 2; ++h){
                        const uint32_t V0 = acc[i][0][h], V1 = acc[i][1][h];
                        const uint32_t V2 = acc[i][2][h], V3 = acc[i][3][h];
                        // send V[tq ^ r]; bfly-xor r returns partner's V[tq]
                        const uint32_t s0 = tq==0?V0: tq==1?V1: tq==2?V2:V3;
                        const uint32_t s1 = tq==0?V1: tq==1?V0: tq==2?V3:V2;
                        const uint32_t s2 = tq==0?V2: tq==1?V3: tq==2?V0:V1;
                        const uint32_t s3 = tq==0?V3: tq==1?V2: tq==2?V1:V0;
                        uint32_t T0 = s0;
                        uint32_t T1 = __shfl_xor_sync(0xffffffffu, s1, 1);
                        uint32_t T2 = __shfl_xor_sync(0xffffffffu, s2, 2);
                        uint32_t T3 = __shfl_xor_sync(0xffffffffu, s3, 3);
                        // W[p] = T[tq ^ p]: reorder via tq-bit swaps
                        uint32_t A0=T0, A1=T1, A2=T2, A3=T3, tmp;
                        if (tq & 1){ tmp=A0; A0=A1; A1=tmp; tmp=A2; A2=A3; A3=tmp; }
                        if (tq & 2){ tmp=A0; A0=A2; A2=tmp; tmp=A1; A1=A3; A3=tmp; }
                        uint4 o;
                        ((__half2*)&o)[0] = __hadd2(*(__half2*)&A0, bb2[0]);
                        ((__half2*)&o)[1] = __hadd2(*(__half2*)&A1, bb2[1]);
                        ((__half2*)&o)[2] = __hadd2(*(__half2*)&A2, bb2[2]);
                        ((__half2*)&o)[3] = __hadd2(*(__half2*)&A3, bb2[3]);
                        *(uint4*)(drow + h*8*768) = o;
                    }
                }
            }
            __syncthreads();
        }
    }
}

// ---------------- fused attention + proj GEMM + bias + residual ---------------
// CTA: one batch-pair x 64 pixels (128 tokens, view-major). 256 threads,
// 2 CTAs/SM. Phase 1: warp-per-pixel attention -> ao into Bs K-chunks.
// Phase 2: proj GEMM 128 tok x 256 ch (2 M-iters, 2 K-chunks), fp32 accum,
// warp tile 32ch x 64tok; fused bias + residual + direct float2 NCHW stores.
__global__ __launch_bounds__(256, 2) void k_proj(
    const float* __restrict__ x, const float* __restrict__ bproj, float* __restrict__ out)
{
    extern __shared__ __half sm[];
    __half* Bs = sm;               // [2 kc][128 tok][PCH] attention out
    __half* As = sm + 2*CHUNK;     // [128 ch][PCH] weights
    const int t  = threadIdx.x;
    const int b  = blockIdx.y;            // pair index
    const int p0 = blockIdx.x * 64;
    const int lane = t & 31, warp = t >> 5;

    // ---- phase 1: attention (8 pixels per warp) ----
    {
        const int off = (lane >> 3)*64 + (lane & 7)*8;   // channel offset 0..255
        const int chunk = off >> 7, cin = off & 127;
        #pragma unroll 2
        for (int itr = 0; itr < 8; ++itr){
            const int pix = warp*8 + itr;
            const __half* r0 = g_qkvT + ((size_t)(b*2*HW + p0 + pix))*768;
            const __half* r1 = r0 + (size_t)HW*768;
            float q0[8],q1[8],k0[8],k1[8],v0[8],v1[8];
            {
                uint4 u; const __half2* h = (const __half2*)&u; float2 f;
                #define LD8(dst, ptr) { u = *(const uint4*)(ptr); \
                    _Pragma("unroll") for (int e = 0; e < 4; ++e){ f = __half22float2(h[e]); dst[2*e]=f.x; dst[2*e+1]=f.y; } }
                LD8(q0, r0 + off);        LD8(q1, r1 + off);
                LD8(k0, r0 + 256 + off);  LD8(k1, r1 + 256 + off);
                LD8(v0, r0 + 512 + off);  LD8(v1, r1 + 512 + off);
                #undef LD8
            }
            float s00=0.f, s01=0.f, s10=0.f, s11=0.f;
            #pragma unroll
            for (int j = 0; j < 8; ++j){
                s00 += q0[j]*k0[j]; s01 += q0[j]*k1[j];
                s10 += q1[j]*k0[j]; s11 += q1[j]*k1[j];
            }
            #pragma unroll
            for (int d = 1; d < 8; d <<= 1){
                s00 += __shfl_xor_sync(0xffffffffu, s00, d);
                s01 += __shfl_xor_sync(0xffffffffu, s01, d);
                s10 += __shfl_xor_sync(0xffffffffu, s10, d);
                s11 += __shfl_xor_sync(0xffffffffu, s11, d);
            }
            const float sc = 0.125f;
            const float l00=s00*sc, l01=s01*sc, l10=s10*sc, l11=s11*sc;
            const float m0 = fmaxf(l00,l01), m1 = fmaxf(l10,l11);
            const float e00=__expf(l00-m0), e01=__expf(l01-m0);
            const float e10=__expf(l10-m1), e11=__expf(l11-m1);
            const float i0 = 1.f/(e00+e01), i1 = 1.f/(e10+e11);
            const float a00=e00*i0, a01=e01*i0, a10=e10*i1, a11=e11*i1;
            __align__(16) __half o0[8], o1[8];
            #pragma unroll
            for (int j = 0; j < 8; ++j){
                o0[j] = __float2half(a00*v0[j] + a01*v1[j]);
                o1[j] = __float2half(a10*v0[j] + a11*v1[j]);
            }
            *(uint4*)(Bs + chunk*CHUNK + pix*PCH + cin)        = *(const uint4*)o0;
            *(uint4*)(Bs + chunk*CHUNK + (64 + pix)*PCH + cin) = *(const uint4*)o1;
        }
    }
    loadA<256>(As, g_wproj, t);    // (mt=0, kc=0)
    __syncthreads();

    // ---- phase 2: proj GEMM (fp32 accumulate) ----
    const int g = lane >> 2, tq = lane & 3;
    const int lrow  = lane & 15;
    const int khalf = lane >> 4;
    const int mwarp = (warp & 3) * 32;    // channel offset (4 groups of 32)
    const int twarp = (warp >> 2) * 64;   // token offset (view0/view1)
    const int view  = warp >> 2;

    uint32_t aB[2], bB[4];
    #pragma unroll
    for (int i = 0; i < 2; ++i)
        aB[i] = s2u(As + (mwarp + i*16 + lrow)*PCH) + khalf*16;
    #pragma unroll
    for (int j = 0; j < 4; ++j)
        bB[j] = s2u(Bs + (twarp + j*16 + lrow)*PCH) + khalf*16;

    #pragma unroll 1
    for (int mt = 0; mt < 2; ++mt){
        float acc[2][8][4];
        #pragma unroll
        for (int i=0;i<2;i++)
            #pragma unroll
            for (int j=0;j<8;j++)
                #pragma unroll
                for (int r=0;r<4;r++) acc[i][j][r]=0.f;

        #pragma unroll 1
        for (int kc = 0; kc < 2; ++kc){
            const uint32_t boff = (uint32_t)kc * CHUNK_B;
            #pragma unroll
            for (int ks = 0; ks < 8; ++ks){
                uint32_t ra[2][4], rb[4][4];
                #pragma unroll
                for (int i = 0; i < 2; ++i) ldsm4(ra[i], aB[i] + ks*32);
                #pragma unroll
                for (int j = 0; j < 4; ++j) ldsm4(rb[j], bB[j] + boff + ks*32);
                #pragma unroll
                for (int i = 0; i < 2; ++i)
                    #pragma unroll
                    for (int j = 0; j < 8; ++j)
                        mma_f(acc[i][j], ra[i],
                              rb[j>>1][j&1], rb[j>>1][2 + (j&1)]);
            }
            __syncthreads();
            if (kc == 0){
                loadA<256>(As, g_wproj + (size_t)mt*128*256 + 128, t);
            } else if (mt == 0){
                loadA<256>(As, g_wproj + (size_t)128*256, t);
            }
            if (kc == 1){
                #pragma unroll
                for (int i = 0; i < 2; ++i){
                    const int ch0 = mt*128 + mwarp + i*16 + g;
                    const int ch1 = ch0 + 8;
                    const float b0 = bproj[ch0], b1 = bproj[ch1];
                    const size_t base0 = ((size_t)((b*2 + view)*256 + ch0))*HW + p0;
                    const size_t base1 = ((size_t)((b*2 + view)*256 + ch1))*HW + p0;
                    #pragma unroll
                    for (int j = 0; j < 8; ++j){
                        const int tk = j*8 + tq*2;
                        float2 xv0 = *(const float2*)(x + base0 + tk);
                        float2 xv1 = *(const float2*)(x + base1 + tk);
                        *(float2*)(out + base0 + tk) =
                            make_float2(xv0.x + acc[i][j][0] + b0, xv0.y + acc[i][j][1] + b0);
                        *(float2*)(out + base1 + tk) =
                            make_float2(xv1.x + acc[i][j][2] + b1, xv1.y + acc[i][j][3] + b1);
                    }
                }
            }
            __syncthreads();
        }
    }
}

// ---------------- launch -------------------------------------------------------
extern "C" void kernel_launch(void* const* d_in, const int* in_sizes, int n_in,
                              void* d_out, int out_size)
{
    const float* x     = (const float*)d_in[0];
    const float* gam   = (const float*)d_in[1];
    const float* bet   = (const float*)d_in[2];
    const float* wqkv  = (const float*)d_in[3];
    const float* bqkv  = (const float*)d_in[4];
    const float* wproj = (const float*)d_in[5];
    const float* bproj = (const float*)d_in[6];
    float* out = (float*)d_out;

    cudaFuncSetAttribute(k_qkv,  cudaFuncAttributeMaxDynamicSharedMemorySize, FUSE_SMEM);
    cudaFuncSetAttribute(k_proj, cudaFuncAttributeMaxDynamicSharedMemorySize, FUSE_SMEM);

    k_convert<<<768, 256>>>(wqkv, wproj, bqkv);
    k_stats<<<dim3(64, 8), 256>>>(x);
    k_statfin<<<1, 64>>>();
    k_qkv<<<dim3(128, 8), 256, FUSE_SMEM>>>(x, gam, bet);
    k_proj<<<dim3(256, 4), 256, FUSE_SMEM>>>(x, bproj, out);
}

// round 17
// speedup vs baseline: 1.2020x; 1.1297x over previous
#include <cuda_runtime.h>
#include <cuda_fp16.h>
#include <cstdint>

#define HW 16384
#define PCH 136                    // halves per 128-k chunk row (128 + 8 pad)
#define CHUNK (128*PCH)            // halves per 128-row chunk
#define CHUNK_B (CHUNK*2)          // bytes per chunk (34816)
#define SMEM_TOTAL (3*CHUNK_B + 4096)  // Bs 2 chunks + As/D 1 chunk + scores

// ---------------- scratch (device globals; no allocations allowed) ----------
__device__ __half g_wqkv2[768*256];   // head-interleaved qkv weights
__device__ __half g_bq2[768];         // permuted qkv bias (fp16)
__device__ __half g_wproj[256*256];
__device__ float g_part[64][8][2];
__device__ float g_mean[64];
__device__ float g_rstd[64];

// ---------------- helpers ----------------------------------------------------
__device__ __forceinline__ uint32_t s2u(const void* p){
    return (uint32_t)__cvta_generic_to_shared(p);
}
__device__ __forceinline__ void ldsm4(uint32_t r[4], uint32_t addr){
    asm volatile("ldmatrix.sync.aligned.m8n8.x4.shared.b16 {%0,%1,%2,%3}, [%4];"
        : "=r"(r[0]), "=r"(r[1]), "=r"(r[2]), "=r"(r[3]) : "r"(addr));
}
__device__ __forceinline__ void mma_h(uint32_t c[2], const uint32_t a[4],
                                      uint32_t b0, uint32_t b1){
    asm volatile(
      "mma.sync.aligned.m16n8k16.row.col.f16.f16.f16.f16 "
      "{%0,%1},{%2,%3,%4,%5},{%6,%7},{%0,%1};\n"
      : "+r"(c[0]), "+r"(c[1])
      : "r"(a[0]), "r"(a[1]), "r"(a[2]), "r"(a[3]), "r"(b0), "r"(b1));
}
__device__ __forceinline__ void mma_f(float c[4], const uint32_t a[4],
                                      uint32_t b0, uint32_t b1){
    asm volatile(
      "mma.sync.aligned.m16n8k16.row.col.f32.f16.f16.f32 "
      "{%0,%1,%2,%3},{%4,%5,%6,%7},{%8,%9},{%0,%1,%2,%3};\n"
      : "+f"(c[0]), "+f"(c[1]), "+f"(c[2]), "+f"(c[3])
      : "r"(a[0]), "r"(a[1]), "r"(a[2]), "r"(a[3]), "r"(b0), "r"(b1));
}

// load a [128 rows][128 k] fp16 half-K weight tile into smem [128][PCH].
__device__ __forceinline__ void loadA(__half* As, const __half* W, int t){
    #pragma unroll
    for (int it = 0; it < 8; ++it){
        const int lin = it*256 + t;
        const int r = lin >> 4, seg = lin & 15;
        *(uint4*)(As + r*PCH + seg*8) = *(const uint4*)(W + r*256 + seg*8);
    }
}

// ---------------- weight convert + head-interleave permutation ----------------
// tile h<4: rows [q_h(64) ; k_h(64)]; tiles 4,5: v rows 512.. / 640..
__global__ void k_convert(const float* __restrict__ wq, const float* __restrict__ wp,
                          const float* __restrict__ bq){
    int i = blockIdx.x*256 + threadIdx.x;
    if (i < 768*256){
        const int row = i >> 8, col = i & 255;
        const int tile = row >> 7, r = row & 127;
        const int src = (tile < 4)
            ? ((r < 64) ? tile*64 + r : 256 + tile*64 + (r - 64))
            : 512 + (tile - 4)*128 + r;
        g_wqkv2[i] = __float2half(wq[src*256 + col]);
        if (col == 0) g_bq2[row] = __float2half(bq[src]);
    }
    if (i < 256*256) g_wproj[i] = __float2half(wp[i]);
}

// ---------------- GroupNorm statistics ---------------------------------------
__global__ void k_stats(const float* __restrict__ x){
    const int gi = blockIdx.x, ck = blockIdx.y, t = threadIdx.x;
    const float4* p = (const float4*)(x + (size_t)gi*524288 + (size_t)ck*65536);
    float s = 0.f, ss = 0.f;
    #pragma unroll 4
    for (int it = 0; it < 64; ++it){
        float4 v = p[it*256 + t];
        s  += v.x + v.y + v.z + v.w;
        ss += v.x*v.x + v.y*v.y + v.z*v.z + v.w*v.w;
    }
    #pragma unroll
    for (int d = 16; d; d >>= 1){
        s  += __shfl_xor_sync(0xffffffffu, s, d);
        ss += __shfl_xor_sync(0xffffffffu, ss, d);
    }
    __shared__ float sh[16];
    if ((t & 31) == 0){ sh[t>>5] = s; sh[8 + (t>>5)] = ss; }
    __syncthreads();
    if (t == 0){
        float S = 0.f, SS = 0.f;
        for (int i = 0; i < 8; ++i){ S += sh[i]; SS += sh[8+i]; }
        g_part[gi][ck][0] = S; g_part[gi][ck][1] = SS;
    }
}

__global__ void k_statfin(){
    const int t = threadIdx.x;
    float S = 0.f, SS = 0.f;
    for (int i = 0; i < 8; ++i){ S += g_part[t][i][0]; SS += g_part[t][i][1]; }
    const float inv = 1.f/524288.f;
    const float m = S*inv;
    const float v = SS*inv - m*m;
    g_mean[t] = m;
    g_rstd[t] = rsqrtf(v + 1e-5f);
}

// ---------------- per-head score dot (from staged D in smem) ------------------
__device__ __forceinline__ void score_head(const __half* D, float* scoresF,
                                           int h, int t){
    const int pix = t >> 2, vq = (t >> 1) & 1, vk = t & 1;
    const __half* Q = D + (vq*64 + pix)*PCH;
    const __half* K = D + (vk*64 + pix)*PCH + 64;
    __half2 acc2 = __float2half2_rn(0.f);
    #pragma unroll
    for (int r = 0; r < 8; ++r){
        uint4 uq = *(const uint4*)(Q + r*8);
        uint4 uk = *(const uint4*)(K + r*8);
        const __half2* qh = (const __half2*)&uq;
        const __half2* kh = (const __half2*)&uk;
        #pragma unroll
        for (int e = 0; e < 4; ++e) acc2 = __hfma2(qh[e], kh[e], acc2);
    }
    const float s = (__low2float(acc2) + __high2float(acc2)) * 0.125f;
    scoresF[((pix*4 + h)*2 + vq)*2 + vk] = s;
}

// ---------------- per-tile attention apply (v tiles) --------------------------
__device__ __forceinline__ void v_apply(const __half* D, const float* scoresF,
                                        int hbase, int t, uint4 ao[8]){
    const int tok = t >> 1, seg = t & 1;
    const int pix = tok & 63, view = tok >> 6;
    const int head = hbase + seg;
    const float s0 = scoresF[((pix*4 + head)*2 + view)*2 + 0];
    const float s1 = scoresF[((pix*4 + head)*2 + view)*2 + 1];
    const float mm = fmaxf(s0, s1);
    const float e0 = __expf(s0 - mm), e1 = __expf(s1 - mm);
    const float inv = 1.f/(e0 + e1);
    const __half2 a0 = __float2half2_rn(e0*inv);
    const __half2 a1 = __float2half2_rn(e1*inv);
    const __half* V0 = D + pix*PCH + seg*64;
    const __half* V1 = D + (64 + pix)*PCH + seg*64;
    #pragma unroll
    for (int r = 0; r < 8; ++r){
        uint4 u0 = *(const uint4*)(V0 + r*8);
        uint4 u1 = *(const uint4*)(V1 + r*8);
        uint4 o;
        const __half2* h0 = (const __half2*)&u0;
        const __half2* h1 = (const __half2*)&u1;
        __half2* oh = (__half2*)&o;
        #pragma unroll
        for (int e = 0; e < 4; ++e)
            oh[e] = __hfma2(a1, h1[e], __hmul2(a0, h0[e]));
        ao[r] = o;
    }
}

// ---------------- mega kernel: GN-apply + QKV GEMM + attention + proj ---------
// CTA = pair b x 64 pixels; tokens = 128 (64 pix x 2 views). 256 thr, 2 CTAs/SM.
// mt 0-3: head tiles [q_h;k_h] -> stage D -> scores. mt 4,5: v tiles -> apply
// attention -> ao in regs. ao -> Bs (K-chunked), then proj GEMM + residual.
__global__ __launch_bounds__(256, 2) void k_main(
    const float* __restrict__ x, const float* __restrict__ gamma,
    const float* __restrict__ beta, const float* __restrict__ bproj,
    float* __restrict__ out)
{
    extern __shared__ __half sm[];
    __half* Bs = sm;               // [2 kc][128 tok][PCH]
    __half* As = sm + 2*CHUNK;     // weights / staged-D region
    float* scoresF = (float*)(sm + 3*CHUNK);   // [64 pix][4 head][2 vq][2 vk]
    const int t  = threadIdx.x;
    const int b  = blockIdx.y;            // pair index
    const int p0 = blockIdx.x * 64;
    const int lane = t & 31, warp = t >> 5;

    // ---- fill Bs: normalized x -> fp16, tokens = (view, pixel) ----
    #pragma unroll
    for (int it = 0; it < 16; ++it){
        const int c = (it*8 + warp) * 2;
        const int g0 = b*16 + (c >> 5);       // bv = 2b
        const int g1 = g0 + 8;                // bv = 2b+1
        const float mu0 = g_mean[g0], rs0 = g_rstd[g0];
        const float mu1 = g_mean[g1], rs1 = g_rstd[g1];
        const float ga0 = gamma[c], ga1 = gamma[c+1];
        const float be0 = beta[c],  be1 = beta[c+1];
        const float sA0 = rs0*ga0, hA0 = be0 - mu0*sA0;
        const float sA1 = rs0*ga1, hA1 = be1 - mu0*sA1;
        const float sB0 = rs1*ga0, hB0 = be0 - mu1*sB0;
        const float sB1 = rs1*ga1, hB1 = be1 - mu1*sB1;
        const float* x00 = x + ((size_t)((2*b)*256 + c))*HW + p0;
        const float* x01 = x00 + HW;
        const float* x10 = x + ((size_t)((2*b+1)*256 + c))*HW + p0;
        const float* x11 = x10 + HW;
        __half* dst = Bs + (c >> 7)*CHUNK + (c & 127);
        #pragma unroll
        for (int i = 0; i < 4; ++i){
            const int j = i*32 + lane;        // token 0..127
            const int pix = j & 63;
            __half2 v;
            if (i < 2) v = __floats2half2_rn(x00[pix]*sA0 + hA0, x01[pix]*sA1 + hA1);
            else       v = __floats2half2_rn(x10[pix]*sB0 + hB0, x11[pix]*sB1 + hB1);
            *(__half2*)(dst + j*PCH) = v;
        }
    }
    loadA(As, g_wqkv2, t);     // tile0, kc0
    __syncthreads();

    const int g = lane >> 2, tq = lane & 3;
    const int lrow  = lane & 15;
    const int khalf = lane >> 4;
    const int twarp = (warp >> 2) * 64;   // token offset (2 groups of 64)
    const int mwarp = (warp & 3) * 32;    // m offset     (4 groups of 32)

    uint32_t aB[4], bB[2];
    #pragma unroll
    for (int i = 0; i < 4; ++i)
        aB[i] = s2u(Bs + (twarp + i*16 + lrow)*PCH) + khalf*16;
    #pragma unroll
    for (int j = 0; j < 2; ++j)
        bB[j] = s2u(As + (mwarp + j*16 + lrow)*PCH) + khalf*16;

    uint4 ao1[8], ao2[8];

    #pragma unroll 1
    for (int mt = 0; mt < 6; ++mt){
        uint32_t acc[4][4][2];
        #pragma unroll
        for (int i=0;i<4;i++)
            #pragma unroll
            for (int j=0;j<4;j++){ acc[i][j][0]=0u; acc[i][j][1]=0u; }

        #pragma unroll 1
        for (int kc = 0; kc < 2; ++kc){
            const uint32_t boff = (uint32_t)kc * CHUNK_B;
            #pragma unroll
            for (int ks = 0; ks < 8; ++ks){
                uint32_t ra[4][4], rb[2][4];
                #pragma unroll
                for (int i = 0; i < 4; ++i) ldsm4(ra[i], aB[i] + boff + ks*32);
                #pragma unroll
                for (int j = 0; j < 2; ++j) ldsm4(rb[j], bB[j] + ks*32);
                #pragma unroll
                for (int i = 0; i < 4; ++i)
                    #pragma unroll
                    for (int j = 0; j < 4; ++j)
                        mma_h(acc[i][j], ra[i],
                              rb[j>>1][j&1], rb[j>>1][2 + (j&1)]);
            }
            __syncthreads();
            if (kc == 0){
                loadA(As, g_wqkv2 + (size_t)mt*128*256 + 128, t);
                __syncthreads();
            }
        }

        // ---- stage D (+bias, quad transpose) into As region as [tok][PCH] ----
        {
            const uint4 bu = *(const uint4*)(g_bq2 + mt*128 + mwarp + tq*8);
            const __half2* bb2 = (const __half2*)&bu;
            #pragma unroll
            for (int i = 0; i < 4; ++i){
                const int tokA = twarp + i*16 + g;
                __half* drow = As + tokA*PCH + mwarp + tq*8;
                #pragma unroll
                for (int h = 0; h < 2; ++h){
                    const uint32_t V0 = acc[i][0][h], V1 = acc[i][1][h];
                    const uint32_t V2 = acc[i][2][h], V3 = acc[i][3][h];
                    const uint32_t s0 = tq==0?V0: tq==1?V1: tq==2?V2:V3;
                    const uint32_t s1 = tq==0?V1: tq==1?V0: tq==2?V3:V2;
                    const uint32_t s2 = tq==0?V2: tq==1?V3: tq==2?V0:V1;
                    const uint32_t s3 = tq==0?V3: tq==1?V2: tq==2?V1:V0;
                    uint32_t T0 = s0;
                    uint32_t T1 = __shfl_xor_sync(0xffffffffu, s1, 1);
                    uint32_t T2 = __shfl_xor_sync(0xffffffffu, s2, 2);
                    uint32_t T3 = __shfl_xor_sync(0xffffffffu, s3, 3);
                    uint32_t A0=T0, A1=T1, A2=T2, A3=T3, tmp;
                    if (tq & 1){ tmp=A0; A0=A1; A1=tmp; tmp=A2; A2=A3; A3=tmp; }
                    if (tq & 2){ tmp=A0; A0=A2; A2=tmp; tmp=A1; A1=A3; A3=tmp; }
                    uint4 o;
                    ((__half2*)&o)[0] = __hadd2(*(__half2*)&A0, bb2[0]);
                    ((__half2*)&o)[1] = __hadd2(*(__half2*)&A1, bb2[1]);
                    ((__half2*)&o)[2] = __hadd2(*(__half2*)&A2, bb2[2]);
                    ((__half2*)&o)[3] = __hadd2(*(__half2*)&A3, bb2[3]);
                    *(uint4*)(drow + h*8*PCH) = o;
                }
            }
        }
        __syncthreads();

        if (mt < 4)       score_head(As, scoresF, mt, t);
        else if (mt == 4) v_apply(As, scoresF, 0, t, ao1);
        else              v_apply(As, scoresF, 2, t, ao2);
        __syncthreads();

        if (mt < 5){
            loadA(As, g_wqkv2 + (size_t)(mt + 1)*128*256, t);
            __syncthreads();
        }
    }

    // ---- write ao -> Bs (K-chunked token-major) + load proj weights ----
    {
        const int tok = t >> 1, seg = t & 1;
        __half* d0 = Bs + tok*PCH + seg*64;
        __half* d1 = Bs + CHUNK + tok*PCH + seg*64;
        #pragma unroll
        for (int r = 0; r < 8; ++r){
            *(uint4*)(d0 + r*8) = ao1[r];
            *(uint4*)(d1 + r*8) = ao2[r];
        }
    }
    loadA(As, g_wproj, t);     // pmt0 kc0
    __syncthreads();

    // ---- proj GEMM (fp32 accum) + bias + residual + NCHW stores ----
    const int pmwarp = (warp & 3) * 32;
    const int ptwarp = (warp >> 2) * 64;
    const int view   = warp >> 2;

    uint32_t paB[2], pbB[4];
    #pragma unroll
    for (int i = 0; i < 2; ++i)
        paB[i] = s2u(As + (pmwarp + i*16 + lrow)*PCH) + khalf*16;
    #pragma unroll
    for (int j = 0; j < 4; ++j)
        pbB[j] = s2u(Bs + (ptwarp + j*16 + lrow)*PCH) + khalf*16;

    #pragma unroll 1
    for (int pmt = 0; pmt < 2; ++pmt){
        float facc[2][8][4];
        #pragma unroll
        for (int i=0;i<2;i++)
            #pragma unroll
            for (int j=0;j<8;j++)
                #pragma unroll
                for (int r=0;r<4;r++) facc[i][j][r]=0.f;

        #pragma unroll 1
        for (int kc = 0; kc < 2; ++kc){
            const uint32_t boff = (uint32_t)kc * CHUNK_B;
            #pragma unroll
            for (int ks = 0; ks < 8; ++ks){
                uint32_t ra[2][4], rb[4][4];
                #pragma unroll
                for (int i = 0; i < 2; ++i) ldsm4(ra[i], paB[i] + ks*32);
                #pragma unroll
                for (int j = 0; j < 4; ++j) ldsm4(rb[j], pbB[j] + boff + ks*32);
                #pragma unroll
                for (int i = 0; i < 2; ++i)
                    #pragma unroll
                    for (int j = 0; j < 8; ++j)
                        mma_f(facc[i][j], ra[i],
                              rb[j>>1][j&1], rb[j>>1][2 + (j&1)]);
            }
            __syncthreads();
            if (kc == 0){
                loadA(As, g_wproj + (size_t)pmt*128*256 + 128, t);
            } else if (pmt == 0){
                loadA(As, g_wproj + (size_t)128*256, t);
            }
            if (kc == 1){
                #pragma unroll
                for (int i = 0; i < 2; ++i){
                    const int ch0 = pmt*128 + pmwarp + i*16 + g;
                    const int ch1 = ch0 + 8;
                    const float b0 = bproj[ch0], b1 = bproj[ch1];
                    const size_t base0 = ((size_t)((b*2 + view)*256 + ch0))*HW + p0;
                    const size_t base1 = ((size_t)((b*2 + view)*256 + ch1))*HW + p0;
                    #pragma unroll
                    for (int j = 0; j < 8; ++j){
                        const int tk = j*8 + tq*2;
                        float2 xv0 = *(const float2*)(x + base0 + tk);
                        float2 xv1 = *(const float2*)(x + base1 + tk);
                        *(float2*)(out + base0 + tk) =
                            make_float2(xv0.x + facc[i][j][0] + b0, xv0.y + facc[i][j][1] + b0);
                        *(float2*)(out + base1 + tk) =
                            make_float2(xv1.x + facc[i][j][2] + b1, xv1.y + facc[i][j][3] + b1);
                    }
                }
            }
            __syncthreads();
        }
    }
}

// ---------------- launch -------------------------------------------------------
extern "C" void kernel_launch(void* const* d_in, const int* in_sizes, int n_in,
                              void* d_out, int out_size)
{
    const float* x     = (const float*)d_in[0];
    const float* gam   = (const float*)d_in[1];
    const float* bet   = (const float*)d_in[2];
    const float* wqkv  = (const float*)d_in[3];
    const float* bqkv  = (const float*)d_in[4];
    const float* wproj = (const float*)d_in[5];
    const float* bproj = (const float*)d_in[6];
    float* out = (float*)d_out;

    cudaFuncSetAttribute(k_main, cudaFuncAttributeMaxDynamicSharedMemorySize, SMEM_TOTAL);

    k_convert<<<768, 256>>>(wqkv, wproj, bqkv);
    k_stats<<<dim3(64, 8), 256>>>(x);
    k_statfin<<<1, 64>>>();
    k_main<<<dim3(256, 4), 256, SMEM_TOTAL>>>(x, gam, bet, bproj, out);
}